// round 3
// baseline (speedup 1.0000x reference)
#include <cuda_runtime.h>
#include <cuda_bf16.h>

// S4 Vandermonde kernel: out[h,l] = 2*Re( sum_n Ceff[h,n] * w[h,n]^l )
//   w = exp(dtA), Ceff = Bc*Cc*(w-1)/A
// H=512, NH=32, L=8192.
//
// Strategy: geometric recurrence z <- z * w^32 with lane j owning l = base+j+32*i
// (coalesced stores). States/multipliers for 32 modes packed pairwise into
// f32x2 (FFMA2) -> 2.5 fma-pipe instructions per output instead of 5.
// Lane start values built from a per-warp shared table of w^(2^k) computed by
// direct exp with exact power-of-2 angle scaling + two-float 2*pi reduction
// (phase error ~1e-7; recurrence drift bounded to 64 steps).

#define HH 512
#define NHALF 32
#define LL 8192
#define SPT 64                       // recurrence steps per lane
#define WPB 4                        // warps per block
#define CHUNK (32 * SPT)             // 2048 l-values per warp
#define CHUNKS_PER_H (LL / CHUNK)    // 4

typedef unsigned long long u64;

__device__ __forceinline__ u64 pk2(float lo, float hi) {
    u64 r; asm("mov.b64 %0,{%1,%2};" : "=l"(r) : "f"(lo), "f"(hi)); return r;
}
__device__ __forceinline__ void upk2(u64 v, float& lo, float& hi) {
    asm("mov.b64 {%0,%1},%2;" : "=f"(lo), "=f"(hi) : "l"(v));
}
__device__ __forceinline__ u64 f2mul(u64 a, u64 b) {
    u64 r; asm("mul.rn.f32x2 %0,%1,%2;" : "=l"(r) : "l"(a), "l"(b)); return r;
}
__device__ __forceinline__ u64 f2fma(u64 a, u64 b, u64 c) {
    u64 r; asm("fma.rn.f32x2 %0,%1,%2,%3;" : "=l"(r) : "l"(a), "l"(b), "l"(c)); return r;
}
__device__ __forceinline__ u64 f2add(u64 a, u64 b) {
    u64 r; asm("add.rn.f32x2 %0,%1,%2;" : "=l"(r) : "l"(a), "l"(b)); return r;
}

__device__ __forceinline__ float2 cmulf(float2 a, float2 b) {
    return make_float2(fmaf(a.x, b.x, -a.y * b.y), fmaf(a.x, b.y, a.y * b.x));
}

__global__ void __launch_bounds__(128)
s4_vandermonde_kernel(const float* __restrict__ log_dt,
                      const float* __restrict__ log_A_real,
                      const float* __restrict__ A_imag,
                      const float* __restrict__ Bmat,
                      const float* __restrict__ Cmat,
                      float* __restrict__ out)
{
    // per warp: per mode n: slots 0..5 = w^(2^k) (w^1..w^32), 6 = w^2048,
    // 7 = w^4096, 8 = Ceff
    __shared__ float2 tab[WPB][NHALF][9];

    const int w   = threadIdx.x >> 5;
    const int j   = threadIdx.x & 31;
    const int gw  = blockIdx.x * WPB + w;
    const int h   = gw >> 2;       // / CHUNKS_PER_H
    const int chk = gw & 3;

    // ---------- per-mode setup: lane j handles mode n = j ----------
    {
        const int n = j;
        const float dt  = __expf(log_dt[h]);
        const float ar  = -__expf(log_A_real[h * NHALF + n]);
        const float ai  = -A_imag[h * NHALF + n];
        const float dre = dt * ar;
        const float dim = dt * ai;

        const float PI2_HI = 6.2831854820251465f;
        const float PI2_LO = -1.7484561e-7f;
        const float INV2PI = 0.15915494309189535f;
        const float exps[8] = {1.f, 2.f, 4.f, 8.f, 16.f, 32.f, 2048.f, 4096.f};
        #pragma unroll
        for (int k = 0; k < 8; k++) {
            float e  = exps[k];
            float mg = __expf(dre * e);        // dre*e exact (power-of-2 scale)
            float th = dim * e;                // exact
            float kk = rintf(th * INV2PI);
            float r  = fmaf(-kk, PI2_HI, th);
            r        = fmaf(-kk, PI2_LO, r);
            float s, c;
            __sincosf(r, &s, &c);
            tab[w][n][k] = make_float2(mg * c, mg * s);
        }
        // Ceff = Bc*Cc*(w-1)/A
        float2 w1  = tab[w][n][0];
        float2 num = make_float2(w1.x - 1.0f, w1.y);
        float  inv = 1.0f / (ar * ar + ai * ai);
        float2 ia  = make_float2(ar * inv, -ai * inv);
        float2 bc  = cmulf(make_float2(Bmat[(h * NHALF + n) * 2],
                                       Bmat[(h * NHALF + n) * 2 + 1]),
                           make_float2(Cmat[(h * NHALF + n) * 2],
                                       Cmat[(h * NHALF + n) * 2 + 1]));
        tab[w][n][8] = cmulf(cmulf(bc, num), ia);
    }
    __syncwarp();

    // ---------- start state: z_n = Ceff_n * w_n^(chk*2048 + j) ----------
    float xs[NHALF], ys[NHALF];
    #pragma unroll
    for (int n = 0; n < NHALF; n++) {
        float2 p = make_float2(1.f, 0.f);
        #pragma unroll
        for (int k = 0; k < 5; k++)
            if ((j >> k) & 1) p = cmulf(p, tab[w][n][k]);
        if (chk & 1) p = cmulf(p, tab[w][n][6]);
        if (chk & 2) p = cmulf(p, tab[w][n][7]);
        float2 z = cmulf(p, tab[w][n][8]);
        xs[n] = z.x; ys[n] = z.y;
    }

    // ---------- pack states & constants pairwise into f32x2 ----------
    u64 X[NHALF / 2], Y[NHALF / 2], WR[NHALF / 2], WI[NHALF / 2], NWI[NHALF / 2];
    #pragma unroll
    for (int p = 0; p < NHALF / 2; p++) {
        X[p] = pk2(xs[2 * p], xs[2 * p + 1]);
        Y[p] = pk2(ys[2 * p], ys[2 * p + 1]);
        float2 a = tab[w][2 * p][5];      // w^32 for mode 2p
        float2 b = tab[w][2 * p + 1][5];  // w^32 for mode 2p+1
        WR[p]  = pk2(a.x, b.x);
        WI[p]  = pk2(a.y, b.y);
        NWI[p] = pk2(-a.y, -b.y);
    }

    // ---------- main recurrence: out[l] = 2*sum Re(z); z *= w^32 ----------
    float* op = out + h * LL + chk * CHUNK + j;
    #pragma unroll 4
    for (int i = 0; i < SPT; i++) {
        // reduction tree over current X (real parts of all 32 modes)
        u64 s[NHALF / 2];
        #pragma unroll
        for (int p = 0; p < NHALF / 2; p++) s[p] = X[p];
        #pragma unroll
        for (int st = NHALF / 4; st >= 1; st >>= 1) {
            #pragma unroll
            for (int p = 0; p < st; p++) s[p] = f2add(s[p], s[p + st]);
        }
        float alo, ahi;
        upk2(s[0], alo, ahi);
        op[i * 32] = 2.0f * (alo + ahi);

        // z <- z * w^32 (packed complex multiply, 2 modes per instruction)
        #pragma unroll
        for (int p = 0; p < NHALF / 2; p++) {
            u64 t1 = f2mul(NWI[p], Y[p]);   // (-wim*y)
            u64 t2 = f2mul(WR[p],  Y[p]);   // ( wre*y)
            u64 xn = f2fma(WR[p], X[p], t1);
            Y[p]   = f2fma(WI[p], X[p], t2);
            X[p]   = xn;
        }
    }
}

extern "C" void kernel_launch(void* const* d_in, const int* in_sizes, int n_in,
                              void* d_out, int out_size)
{
    const float* log_dt     = (const float*)d_in[0];
    const float* log_A_real = (const float*)d_in[1];
    const float* A_imag     = (const float*)d_in[2];
    const float* Bmat       = (const float*)d_in[3];
    const float* Cmat       = (const float*)d_in[4];
    float* out = (float*)d_out;

    dim3 grid(HH * CHUNKS_PER_H / WPB);   // 512 blocks
    dim3 block(32 * WPB);                 // 128 threads
    s4_vandermonde_kernel<<<grid, block>>>(log_dt, log_A_real, A_imag,
                                           Bmat, Cmat, out);
}

// round 4
// speedup vs baseline: 1.0018x; 1.0018x over previous
#include <cuda_runtime.h>
#include <cuda_bf16.h>

// S4 Vandermonde kernel: out[h,l] = 2*Re( sum_n Ceff[h,n] * w[h,n]^l )
//   w = exp(dtA), Ceff = Bc*Cc*(w-1)/A
// H=512, NH=32, L=8192.
//
// Strategy: geometric recurrence z <- z * w^32 with lane j owning l = base+j+32*i
// (coalesced stores). States/multipliers for 32 modes packed pairwise into
// f32x2 (FFMA2) -> 2.5 fma-pipe instructions per output instead of 5.
// Lane start values built from a per-warp shared table of w^(2^k) computed by
// direct exp with exact power-of-2 angle scaling + two-float 2*pi reduction
// (phase error ~1e-7; recurrence drift bounded to 64 steps).

#define HH 512
#define NHALF 32
#define LL 8192
#define SPT 64                       // recurrence steps per lane
#define WPB 4                        // warps per block
#define CHUNK (32 * SPT)             // 2048 l-values per warp
#define CHUNKS_PER_H (LL / CHUNK)    // 4

typedef unsigned long long u64;

__device__ __forceinline__ u64 pk2(float lo, float hi) {
    u64 r; asm("mov.b64 %0,{%1,%2};" : "=l"(r) : "f"(lo), "f"(hi)); return r;
}
__device__ __forceinline__ void upk2(u64 v, float& lo, float& hi) {
    asm("mov.b64 {%0,%1},%2;" : "=f"(lo), "=f"(hi) : "l"(v));
}
__device__ __forceinline__ u64 f2mul(u64 a, u64 b) {
    u64 r; asm("mul.rn.f32x2 %0,%1,%2;" : "=l"(r) : "l"(a), "l"(b)); return r;
}
__device__ __forceinline__ u64 f2fma(u64 a, u64 b, u64 c) {
    u64 r; asm("fma.rn.f32x2 %0,%1,%2,%3;" : "=l"(r) : "l"(a), "l"(b), "l"(c)); return r;
}
__device__ __forceinline__ u64 f2add(u64 a, u64 b) {
    u64 r; asm("add.rn.f32x2 %0,%1,%2;" : "=l"(r) : "l"(a), "l"(b)); return r;
}

__device__ __forceinline__ float2 cmulf(float2 a, float2 b) {
    return make_float2(fmaf(a.x, b.x, -a.y * b.y), fmaf(a.x, b.y, a.y * b.x));
}

__global__ void __launch_bounds__(128)
s4_vandermonde_kernel(const float* __restrict__ log_dt,
                      const float* __restrict__ log_A_real,
                      const float* __restrict__ A_imag,
                      const float* __restrict__ Bmat,
                      const float* __restrict__ Cmat,
                      float* __restrict__ out)
{
    // per warp: per mode n: slots 0..5 = w^(2^k) (w^1..w^32), 6 = w^2048,
    // 7 = w^4096, 8 = Ceff
    __shared__ float2 tab[WPB][NHALF][9];

    const int w   = threadIdx.x >> 5;
    const int j   = threadIdx.x & 31;
    const int gw  = blockIdx.x * WPB + w;
    const int h   = gw >> 2;       // / CHUNKS_PER_H
    const int chk = gw & 3;

    // ---------- per-mode setup: lane j handles mode n = j ----------
    {
        const int n = j;
        const float dt  = __expf(log_dt[h]);
        const float ar  = -__expf(log_A_real[h * NHALF + n]);
        const float ai  = -A_imag[h * NHALF + n];
        const float dre = dt * ar;
        const float dim = dt * ai;

        const float PI2_HI = 6.2831854820251465f;
        const float PI2_LO = -1.7484561e-7f;
        const float INV2PI = 0.15915494309189535f;
        const float exps[8] = {1.f, 2.f, 4.f, 8.f, 16.f, 32.f, 2048.f, 4096.f};
        #pragma unroll
        for (int k = 0; k < 8; k++) {
            float e  = exps[k];
            float mg = __expf(dre * e);        // dre*e exact (power-of-2 scale)
            float th = dim * e;                // exact
            float kk = rintf(th * INV2PI);
            float r  = fmaf(-kk, PI2_HI, th);
            r        = fmaf(-kk, PI2_LO, r);
            float s, c;
            __sincosf(r, &s, &c);
            tab[w][n][k] = make_float2(mg * c, mg * s);
        }
        // Ceff = Bc*Cc*(w-1)/A
        float2 w1  = tab[w][n][0];
        float2 num = make_float2(w1.x - 1.0f, w1.y);
        float  inv = 1.0f / (ar * ar + ai * ai);
        float2 ia  = make_float2(ar * inv, -ai * inv);
        float2 bc  = cmulf(make_float2(Bmat[(h * NHALF + n) * 2],
                                       Bmat[(h * NHALF + n) * 2 + 1]),
                           make_float2(Cmat[(h * NHALF + n) * 2],
                                       Cmat[(h * NHALF + n) * 2 + 1]));
        tab[w][n][8] = cmulf(cmulf(bc, num), ia);
    }
    __syncwarp();

    // ---------- start state: z_n = Ceff_n * w_n^(chk*2048 + j) ----------
    float xs[NHALF], ys[NHALF];
    #pragma unroll
    for (int n = 0; n < NHALF; n++) {
        float2 p = make_float2(1.f, 0.f);
        #pragma unroll
        for (int k = 0; k < 5; k++)
            if ((j >> k) & 1) p = cmulf(p, tab[w][n][k]);
        if (chk & 1) p = cmulf(p, tab[w][n][6]);
        if (chk & 2) p = cmulf(p, tab[w][n][7]);
        float2 z = cmulf(p, tab[w][n][8]);
        xs[n] = z.x; ys[n] = z.y;
    }

    // ---------- pack states & constants pairwise into f32x2 ----------
    u64 X[NHALF / 2], Y[NHALF / 2], WR[NHALF / 2], WI[NHALF / 2], NWI[NHALF / 2];
    #pragma unroll
    for (int p = 0; p < NHALF / 2; p++) {
        X[p] = pk2(xs[2 * p], xs[2 * p + 1]);
        Y[p] = pk2(ys[2 * p], ys[2 * p + 1]);
        float2 a = tab[w][2 * p][5];      // w^32 for mode 2p
        float2 b = tab[w][2 * p + 1][5];  // w^32 for mode 2p+1
        WR[p]  = pk2(a.x, b.x);
        WI[p]  = pk2(a.y, b.y);
        NWI[p] = pk2(-a.y, -b.y);
    }

    // ---------- main recurrence: out[l] = 2*sum Re(z); z *= w^32 ----------
    float* op = out + h * LL + chk * CHUNK + j;
    #pragma unroll 4
    for (int i = 0; i < SPT; i++) {
        // reduction tree over current X (real parts of all 32 modes)
        u64 s[NHALF / 2];
        #pragma unroll
        for (int p = 0; p < NHALF / 2; p++) s[p] = X[p];
        #pragma unroll
        for (int st = NHALF / 4; st >= 1; st >>= 1) {
            #pragma unroll
            for (int p = 0; p < st; p++) s[p] = f2add(s[p], s[p + st]);
        }
        float alo, ahi;
        upk2(s[0], alo, ahi);
        op[i * 32] = 2.0f * (alo + ahi);

        // z <- z * w^32 (packed complex multiply, 2 modes per instruction)
        #pragma unroll
        for (int p = 0; p < NHALF / 2; p++) {
            u64 t1 = f2mul(NWI[p], Y[p]);   // (-wim*y)
            u64 t2 = f2mul(WR[p],  Y[p]);   // ( wre*y)
            u64 xn = f2fma(WR[p], X[p], t1);
            Y[p]   = f2fma(WI[p], X[p], t2);
            X[p]   = xn;
        }
    }
}

extern "C" void kernel_launch(void* const* d_in, const int* in_sizes, int n_in,
                              void* d_out, int out_size)
{
    const float* log_dt     = (const float*)d_in[0];
    const float* log_A_real = (const float*)d_in[1];
    const float* A_imag     = (const float*)d_in[2];
    const float* Bmat       = (const float*)d_in[3];
    const float* Cmat       = (const float*)d_in[4];
    float* out = (float*)d_out;

    dim3 grid(HH * CHUNKS_PER_H / WPB);   // 512 blocks
    dim3 block(32 * WPB);                 // 128 threads
    s4_vandermonde_kernel<<<grid, block>>>(log_dt, log_A_real, A_imag,
                                           Bmat, Cmat, out);
}

// round 6
// speedup vs baseline: 1.4040x; 1.4015x over previous
#include <cuda_runtime.h>
#include <cuda_bf16.h>

// S4 Vandermonde kernel: out[h,l] = 2*Re( sum_n Ceff[h,n] * w[h,n]^l )
//   w = exp(dtA), Ceff = Bc*Cc*(w-1)/A ;  H=512, NH=32, L=8192.
//
// R5: two-term REAL recurrence (Goertzel): r_i = Re(C2*w^(base+32i)) obeys
//   r_{i+1} = p*r_i + q*r_{i-1},  p = 2*Re(w^32), q = -|w^32|^2
// -> 2 f32x2 ops per mode-pair per step instead of 4 (f32x2 rt=3 due to
// RF banking, so op count is the binding resource). 2x factor folded into
// Ceff. Fix vs R4: w^-32 now stored in slot 9 (was clobbered by Ceff in slot 8).

#define HH 512
#define NHALF 32
#define LL 8192
#define SPT 64                       // recurrence steps per lane
#define WPB 4                        // warps per block
#define CHUNK (32 * SPT)             // 2048 l-values per warp
#define CHUNKS_PER_H (LL / CHUNK)    // 4

typedef unsigned long long u64;

__device__ __forceinline__ u64 pk2(float lo, float hi) {
    u64 r; asm("mov.b64 %0,{%1,%2};" : "=l"(r) : "f"(lo), "f"(hi)); return r;
}
__device__ __forceinline__ void upk2(u64 v, float& lo, float& hi) {
    asm("mov.b64 {%0,%1},%2;" : "=f"(lo), "=f"(hi) : "l"(v));
}
__device__ __forceinline__ u64 f2mul(u64 a, u64 b) {
    u64 r; asm("mul.rn.f32x2 %0,%1,%2;" : "=l"(r) : "l"(a), "l"(b)); return r;
}
__device__ __forceinline__ u64 f2fma(u64 a, u64 b, u64 c) {
    u64 r; asm("fma.rn.f32x2 %0,%1,%2,%3;" : "=l"(r) : "l"(a), "l"(b), "l"(c)); return r;
}
__device__ __forceinline__ u64 f2add(u64 a, u64 b) {
    u64 r; asm("add.rn.f32x2 %0,%1,%2;" : "=l"(r) : "l"(a), "l"(b)); return r;
}

__device__ __forceinline__ float2 cmulf(float2 a, float2 b) {
    return make_float2(fmaf(a.x, b.x, -a.y * b.y), fmaf(a.x, b.y, a.y * b.x));
}

// reduction tree over 16 packed pairs -> scalar (lo+hi)
__device__ __forceinline__ float sumtree16(const u64* R) {
    u64 s0 = f2add(R[0], R[8]);
    u64 s1 = f2add(R[1], R[9]);
    u64 s2 = f2add(R[2], R[10]);
    u64 s3 = f2add(R[3], R[11]);
    u64 s4 = f2add(R[4], R[12]);
    u64 s5 = f2add(R[5], R[13]);
    u64 s6 = f2add(R[6], R[14]);
    u64 s7 = f2add(R[7], R[15]);
    s0 = f2add(s0, s4); s1 = f2add(s1, s5);
    s2 = f2add(s2, s6); s3 = f2add(s3, s7);
    s0 = f2add(s0, s2); s1 = f2add(s1, s3);
    s0 = f2add(s0, s1);
    float lo, hi; upk2(s0, lo, hi);
    return lo + hi;
}

__global__ void __launch_bounds__(128, 3)
s4_vandermonde_kernel(const float* __restrict__ log_dt,
                      const float* __restrict__ log_A_real,
                      const float* __restrict__ A_imag,
                      const float* __restrict__ Bmat,
                      const float* __restrict__ Cmat,
                      float* __restrict__ out)
{
    // per warp, per mode n:
    //  slots 0..4 = w^(2^k) (w^1..w^16), 5 = w^32, 6 = w^2048, 7 = w^4096,
    //  8 = 2*Ceff, 9 = w^-32 (magnitude-clamped)
    __shared__ float2 tab[WPB][NHALF][10];

    const int w   = threadIdx.x >> 5;
    const int j   = threadIdx.x & 31;
    const int gw  = blockIdx.x * WPB + w;
    const int h   = gw >> 2;       // / CHUNKS_PER_H
    const int chk = gw & 3;

    // ---------- per-mode setup: lane j handles mode n = j ----------
    {
        const int n = j;
        const float dt  = __expf(log_dt[h]);
        const float ar  = -__expf(log_A_real[h * NHALF + n]);
        const float ai  = -A_imag[h * NHALF + n];
        const float dre = dt * ar;
        const float dim = dt * ai;

        const float PI2_HI = 6.2831854820251465f;
        const float PI2_LO = -1.7484561e-7f;
        const float INV2PI = 0.15915494309189535f;
        const float exps[9] = {1.f, 2.f, 4.f, 8.f, 16.f, 32.f, 2048.f, 4096.f, -32.f};
        #pragma unroll
        for (int k = 0; k < 9; k++) {
            float e   = exps[k];
            float arg = dre * e;                 // exact (power-of-2 scale)
            arg = fminf(arg, 60.0f);             // clamp: only w^-32 can go huge;
                                                 // when it clamps, q underflowed to 0
            float mg = __expf(arg);
            float th = dim * e;                  // exact
            float kk = rintf(th * INV2PI);
            float r  = fmaf(-kk, PI2_HI, th);
            r        = fmaf(-kk, PI2_LO, r);
            float s, c;
            __sincosf(r, &s, &c);
            const int idx = (k == 8) ? 9 : k;    // w^-32 lives in slot 9
            tab[w][n][idx] = make_float2(mg * c, mg * s);
        }
        // 2*Ceff = 2*Bc*Cc*(w-1)/A  (2x folded here) -> slot 8
        float2 w1  = tab[w][n][0];
        float2 num = make_float2(w1.x - 1.0f, w1.y);
        float  inv = 2.0f / (ar * ar + ai * ai);
        float2 ia  = make_float2(ar * inv, -ai * inv);
        float2 bc  = cmulf(make_float2(Bmat[(h * NHALF + n) * 2],
                                       Bmat[(h * NHALF + n) * 2 + 1]),
                           make_float2(Cmat[(h * NHALF + n) * 2],
                                       Cmat[(h * NHALF + n) * 2 + 1]));
        tab[w][n][8] = cmulf(cmulf(bc, num), ia);
    }
    __syncwarp();

    // ---------- start state per mode: r_0, r_-1, p, q ----------
    float r0s[NHALF], rms[NHALF], pcs[NHALF], qcs[NHALF];
    #pragma unroll
    for (int n = 0; n < NHALF; n++) {
        float2 pw = make_float2(1.f, 0.f);
        #pragma unroll
        for (int k = 0; k < 5; k++)
            if ((j >> k) & 1) pw = cmulf(pw, tab[w][n][k]);
        if (chk & 1) pw = cmulf(pw, tab[w][n][6]);
        if (chk & 2) pw = cmulf(pw, tab[w][n][7]);
        float2 z0 = cmulf(pw, tab[w][n][8]);          // 2*Ceff * w^base
        float2 zm = cmulf(z0, tab[w][n][9]);          // one step back
        float2 v  = tab[w][n][5];                     // w^32
        r0s[n] = z0.x;
        rms[n] = zm.x;
        pcs[n] = v.x + v.x;
        qcs[n] = -fmaf(v.x, v.x, v.y * v.y);
    }

    // ---------- pack pairwise into f32x2 ----------
    u64 RB[NHALF / 2], RA[NHALF / 2], P[NHALF / 2], Q[NHALF / 2];
    #pragma unroll
    for (int p = 0; p < NHALF / 2; p++) {
        RB[p] = pk2(r0s[2 * p], r0s[2 * p + 1]);      // r_0
        RA[p] = pk2(rms[2 * p], rms[2 * p + 1]);      // r_-1
        P[p]  = pk2(pcs[2 * p], pcs[2 * p + 1]);
        Q[p]  = pk2(qcs[2 * p], qcs[2 * p + 1]);
    }

    // ---------- main recurrence, unrolled by 2 with role swap ----------
    float* op = out + h * LL + chk * CHUNK + j;
    #pragma unroll 4
    for (int i = 0; i < SPT; i += 2) {
        op[i * 32] = sumtree16(RB);                   // r_i
        #pragma unroll
        for (int p = 0; p < NHALF / 2; p++)           // RA <- r_{i+1}
            RA[p] = f2fma(P[p], RB[p], f2mul(Q[p], RA[p]));
        op[(i + 1) * 32] = sumtree16(RA);             // r_{i+1}
        #pragma unroll
        for (int p = 0; p < NHALF / 2; p++)           // RB <- r_{i+2}
            RB[p] = f2fma(P[p], RA[p], f2mul(Q[p], RB[p]));
    }
}

extern "C" void kernel_launch(void* const* d_in, const int* in_sizes, int n_in,
                              void* d_out, int out_size)
{
    const float* log_dt     = (const float*)d_in[0];
    const float* log_A_real = (const float*)d_in[1];
    const float* A_imag     = (const float*)d_in[2];
    const float* Bmat       = (const float*)d_in[3];
    const float* Cmat       = (const float*)d_in[4];
    float* out = (float*)d_out;

    dim3 grid(HH * CHUNKS_PER_H / WPB);   // 512 blocks
    dim3 block(32 * WPB);                 // 128 threads
    s4_vandermonde_kernel<<<grid, block>>>(log_dt, log_A_real, A_imag,
                                           Bmat, Cmat, out);
}

// round 7
// speedup vs baseline: 1.5275x; 1.0879x over previous
#include <cuda_runtime.h>
#include <cuda_bf16.h>

// S4 Vandermonde kernel: out[h,l] = 2*Re( sum_n Ceff[h,n] * w[h,n]^l )
//   w = exp(dtA), Ceff = Bc*Cc*(w-1)/A ;  H=512, NH=32, L=8192.
//
// R6: same Goertzel two-term real recurrence as R5
//   r_{i+1} = p*r_i + q*r_{i-1},  p = 2*Re(w^32), q = -|w^32|^2
// but SPT 64 -> 128 (grid 512 -> 256 blocks) so the whole launch fits in ONE
// wave at the regs=166 occupancy cap (444 concurrent blocks). R5 had a
// 68-block second wave running at occ~1 that cost ~25% of wall time.

#define HH 512
#define NHALF 32
#define LL 8192
#define SPT 128                      // recurrence steps per lane
#define WPB 4                        // warps per block
#define CHUNK (32 * SPT)             // 4096 l-values per warp
#define CHUNKS_PER_H (LL / CHUNK)    // 2

typedef unsigned long long u64;

__device__ __forceinline__ u64 pk2(float lo, float hi) {
    u64 r; asm("mov.b64 %0,{%1,%2};" : "=l"(r) : "f"(lo), "f"(hi)); return r;
}
__device__ __forceinline__ void upk2(u64 v, float& lo, float& hi) {
    asm("mov.b64 {%0,%1},%2;" : "=f"(lo), "=f"(hi) : "l"(v));
}
__device__ __forceinline__ u64 f2mul(u64 a, u64 b) {
    u64 r; asm("mul.rn.f32x2 %0,%1,%2;" : "=l"(r) : "l"(a), "l"(b)); return r;
}
__device__ __forceinline__ u64 f2fma(u64 a, u64 b, u64 c) {
    u64 r; asm("fma.rn.f32x2 %0,%1,%2,%3;" : "=l"(r) : "l"(a), "l"(b), "l"(c)); return r;
}
__device__ __forceinline__ u64 f2add(u64 a, u64 b) {
    u64 r; asm("add.rn.f32x2 %0,%1,%2;" : "=l"(r) : "l"(a), "l"(b)); return r;
}

__device__ __forceinline__ float2 cmulf(float2 a, float2 b) {
    return make_float2(fmaf(a.x, b.x, -a.y * b.y), fmaf(a.x, b.y, a.y * b.x));
}

// reduction tree over 16 packed pairs -> scalar (lo+hi)
__device__ __forceinline__ float sumtree16(const u64* R) {
    u64 s0 = f2add(R[0], R[8]);
    u64 s1 = f2add(R[1], R[9]);
    u64 s2 = f2add(R[2], R[10]);
    u64 s3 = f2add(R[3], R[11]);
    u64 s4 = f2add(R[4], R[12]);
    u64 s5 = f2add(R[5], R[13]);
    u64 s6 = f2add(R[6], R[14]);
    u64 s7 = f2add(R[7], R[15]);
    s0 = f2add(s0, s4); s1 = f2add(s1, s5);
    s2 = f2add(s2, s6); s3 = f2add(s3, s7);
    s0 = f2add(s0, s2); s1 = f2add(s1, s3);
    s0 = f2add(s0, s1);
    float lo, hi; upk2(s0, lo, hi);
    return lo + hi;
}

__global__ void __launch_bounds__(128, 3)
s4_vandermonde_kernel(const float* __restrict__ log_dt,
                      const float* __restrict__ log_A_real,
                      const float* __restrict__ A_imag,
                      const float* __restrict__ Bmat,
                      const float* __restrict__ Cmat,
                      float* __restrict__ out)
{
    // per warp, per mode n:
    //  slots 0..4 = w^(2^k) (w^1..w^16), 5 = w^32, 6 = w^4096,
    //  7 = w^-32 (magnitude-clamped), 8 = 2*Ceff
    __shared__ float2 tab[WPB][NHALF][9];

    const int w   = threadIdx.x >> 5;
    const int j   = threadIdx.x & 31;
    const int gw  = blockIdx.x * WPB + w;
    const int h   = gw >> 1;       // / CHUNKS_PER_H
    const int chk = gw & 1;

    // ---------- per-mode setup: lane j handles mode n = j ----------
    {
        const int n = j;
        const float dt  = __expf(log_dt[h]);
        const float ar  = -__expf(log_A_real[h * NHALF + n]);
        const float ai  = -A_imag[h * NHALF + n];
        const float dre = dt * ar;
        const float dim = dt * ai;

        const float PI2_HI = 6.2831854820251465f;
        const float PI2_LO = -1.7484561e-7f;
        const float INV2PI = 0.15915494309189535f;
        const float exps[8] = {1.f, 2.f, 4.f, 8.f, 16.f, 32.f, 4096.f, -32.f};
        #pragma unroll
        for (int k = 0; k < 8; k++) {
            float e   = exps[k];
            float arg = dre * e;                 // exact (power-of-2 scale)
            arg = fminf(arg, 60.0f);             // clamp: only w^-32 can go huge;
                                                 // when it clamps, q underflowed to 0
            float mg = __expf(arg);
            float th = dim * e;                  // exact
            float kk = rintf(th * INV2PI);
            float r  = fmaf(-kk, PI2_HI, th);
            r        = fmaf(-kk, PI2_LO, r);
            float s, c;
            __sincosf(r, &s, &c);
            tab[w][n][k] = make_float2(mg * c, mg * s);
        }
        // 2*Ceff = 2*Bc*Cc*(w-1)/A  (2x folded here) -> slot 8
        float2 w1  = tab[w][n][0];
        float2 num = make_float2(w1.x - 1.0f, w1.y);
        float  inv = 2.0f / (ar * ar + ai * ai);
        float2 ia  = make_float2(ar * inv, -ai * inv);
        float2 bc  = cmulf(make_float2(Bmat[(h * NHALF + n) * 2],
                                       Bmat[(h * NHALF + n) * 2 + 1]),
                           make_float2(Cmat[(h * NHALF + n) * 2],
                                       Cmat[(h * NHALF + n) * 2 + 1]));
        tab[w][n][8] = cmulf(cmulf(bc, num), ia);
    }
    __syncwarp();

    // ---------- start state per mode: r_0, r_-1, p, q ----------
    float r0s[NHALF], rms[NHALF], pcs[NHALF], qcs[NHALF];
    #pragma unroll
    for (int n = 0; n < NHALF; n++) {
        float2 pw = make_float2(1.f, 0.f);
        #pragma unroll
        for (int k = 0; k < 5; k++)
            if ((j >> k) & 1) pw = cmulf(pw, tab[w][n][k]);
        if (chk) pw = cmulf(pw, tab[w][n][6]);        // + 4096
        float2 z0 = cmulf(pw, tab[w][n][8]);          // 2*Ceff * w^base
        float2 zm = cmulf(z0, tab[w][n][7]);          // one step back (w^-32)
        float2 v  = tab[w][n][5];                     // w^32
        r0s[n] = z0.x;
        rms[n] = zm.x;
        pcs[n] = v.x + v.x;
        qcs[n] = -fmaf(v.x, v.x, v.y * v.y);
    }

    // ---------- pack pairwise into f32x2 ----------
    u64 RB[NHALF / 2], RA[NHALF / 2], P[NHALF / 2], Q[NHALF / 2];
    #pragma unroll
    for (int p = 0; p < NHALF / 2; p++) {
        RB[p] = pk2(r0s[2 * p], r0s[2 * p + 1]);      // r_0
        RA[p] = pk2(rms[2 * p], rms[2 * p + 1]);      // r_-1
        P[p]  = pk2(pcs[2 * p], pcs[2 * p + 1]);
        Q[p]  = pk2(qcs[2 * p], qcs[2 * p + 1]);
    }

    // ---------- main recurrence, unrolled by 2 with role swap ----------
    float* op = out + h * LL + chk * CHUNK + j;
    #pragma unroll 4
    for (int i = 0; i < SPT; i += 2) {
        op[i * 32] = sumtree16(RB);                   // r_i
        #pragma unroll
        for (int p = 0; p < NHALF / 2; p++)           // RA <- r_{i+1}
            RA[p] = f2fma(P[p], RB[p], f2mul(Q[p], RA[p]));
        op[(i + 1) * 32] = sumtree16(RA);             // r_{i+1}
        #pragma unroll
        for (int p = 0; p < NHALF / 2; p++)           // RB <- r_{i+2}
            RB[p] = f2fma(P[p], RA[p], f2mul(Q[p], RB[p]));
    }
}

extern "C" void kernel_launch(void* const* d_in, const int* in_sizes, int n_in,
                              void* d_out, int out_size)
{
    const float* log_dt     = (const float*)d_in[0];
    const float* log_A_real = (const float*)d_in[1];
    const float* A_imag     = (const float*)d_in[2];
    const float* Bmat       = (const float*)d_in[3];
    const float* Cmat       = (const float*)d_in[4];
    float* out = (float*)d_out;

    dim3 grid(HH * CHUNKS_PER_H / WPB);   // 256 blocks
    dim3 block(32 * WPB);                 // 128 threads
    s4_vandermonde_kernel<<<grid, block>>>(log_dt, log_A_real, A_imag,
                                           Bmat, Cmat, out);
}